// round 2
// baseline (speedup 1.0000x reference)
#include <cuda_runtime.h>

// ---------------------------------------------------------------------------
// Problem constants (B=1024, D_IN=1024, D_H=4096, D_OUT=1024, SPARSITY=0.5)
// Score concat order: [sW1, sb1, sW2, sb2, sW3, sb3]
// total n = 4194304 + 4096 + 16777216 + 4096 + 4194304 + 1024 = 25175040
// j = int(0.5 * n) = 12587520
// ---------------------------------------------------------------------------
#define NTOT   25175040
#define NTOT4  6293760
#define JRANK  12587520u

// element-space segment ends
#define E0 4194304      // end sW1
#define E1 4198400      // end sb1
#define E2 20975616     // end sW2
#define E3 20979712     // end sb2
#define E4 25174016     // end sW3
// float4-space segment ends
#define F0 1048576
#define F1 1049600
#define F2 5243904
#define F3 5244928
#define F4 6293504

#define TIE_CAP 8192

// ---------------------------------------------------------------------------
// Device scratch (static __device__ arrays: the sanctioned no-alloc workaround)
// ---------------------------------------------------------------------------
__device__ float    g_mw[16777216];   // masked weight scratch (reused per layer)
__device__ float    g_mb[4096];       // masked bias scratch
__device__ float    g_h1[4194304];    // hidden 1  [1024,4096]
__device__ float    g_h2[4194304];    // hidden 2  [1024,4096]
__device__ unsigned g_hist1[4096];
__device__ unsigned g_hist2[1024];
__device__ unsigned g_hist3[1024];
__device__ unsigned g_sel[16];        // 0:bin1 1:cum1 2:bin2 3:cum2 4:KT 5:clt 6:need 7:tiecnt 8:tieth
__device__ int      g_ties[TIE_CAP];

// order-preserving float -> uint key
__device__ __forceinline__ unsigned f2key(float f) {
    unsigned u = __float_as_uint(f);
    return (u & 0x80000000u) ? ~u : (u | 0x80000000u);
}

__device__ __forceinline__ float4 fetch4(int i4,
    const float4* __restrict__ s0, const float4* __restrict__ s1,
    const float4* __restrict__ s2, const float4* __restrict__ s3,
    const float4* __restrict__ s4, const float4* __restrict__ s5)
{
    if (i4 < F0) return s0[i4];
    if (i4 < F1) return s1[i4 - F0];
    if (i4 < F2) return s2[i4 - F1];
    if (i4 < F3) return s3[i4 - F2];
    if (i4 < F4) return s4[i4 - F3];
    return s5[i4 - F4];
}

// ---------------------------------------------------------------------------
// State zeroing
// ---------------------------------------------------------------------------
__global__ void k_zero() {
    int t = threadIdx.x;
    for (int i = t; i < 4096; i += 256) g_hist1[i] = 0;
    for (int i = t; i < 1024; i += 256) { g_hist2[i] = 0; g_hist3[i] = 0; }
    if (t < 16) g_sel[t] = 0;
}

// ---------------------------------------------------------------------------
// Radix-select histograms (level 1: bits[31:20]; 2: bits[19:10]; 3: bits[9:0])
// ---------------------------------------------------------------------------
__global__ void k_hist(int level,
    const float4* __restrict__ s0, const float4* __restrict__ s1,
    const float4* __restrict__ s2, const float4* __restrict__ s3,
    const float4* __restrict__ s4, const float4* __restrict__ s5)
{
    __shared__ unsigned h[4096];
    const int nb = (level == 1) ? 4096 : 1024;
    for (int i = threadIdx.x; i < nb; i += blockDim.x) h[i] = 0;
    __syncthreads();

    unsigned pfx = 0;
    if (level == 2) pfx = g_sel[0];
    else if (level == 3) pfx = (g_sel[0] << 10) | g_sel[2];

    const int stride = gridDim.x * blockDim.x;
    for (int i4 = blockIdx.x * blockDim.x + threadIdx.x; i4 < NTOT4; i4 += stride) {
        float4 v = fetch4(i4, s0, s1, s2, s3, s4, s5);
        float vv[4] = {v.x, v.y, v.z, v.w};
        #pragma unroll
        for (int c = 0; c < 4; c++) {
            unsigned key = f2key(vv[c]);
            if (level == 1) {
                atomicAdd(&h[key >> 20], 1u);
            } else if (level == 2) {
                if ((key >> 20) == pfx) atomicAdd(&h[(key >> 10) & 1023u], 1u);
            } else {
                if ((key >> 10) == pfx) atomicAdd(&h[key & 1023u], 1u);
            }
        }
    }
    __syncthreads();
    unsigned* gh = (level == 1) ? g_hist1 : ((level == 2) ? g_hist2 : g_hist3);
    for (int i = threadIdx.x; i < nb; i += blockDim.x) {
        unsigned c = h[i];
        if (c) atomicAdd(&gh[i], c);
    }
}

// Find the bin containing rank JRANK (0-indexed). cum_before <= J < cum_before+count.
__global__ void k_scan(int level) {
    __shared__ unsigned part[256];
    const unsigned* hist = (level == 1) ? g_hist1 : ((level == 2) ? g_hist2 : g_hist3);
    const int nb = (level == 1) ? 4096 : 1024;
    const int chunk = nb >> 8;
    int t = threadIdx.x;
    unsigned s = 0;
    for (int i = 0; i < chunk; i++) s += hist[t * chunk + i];
    part[t] = s;
    __syncthreads();
    if (t == 0) {
        unsigned c = (level == 1) ? 0u : ((level == 2) ? g_sel[1] : g_sel[3]);
        int ch = 0;
        for (; ch < 255; ch++) {
            if (c + part[ch] > JRANK) break;
            c += part[ch];
        }
        int b = ch * chunk;
        for (;; b++) {
            unsigned hh = hist[b];
            if (c + hh > JRANK) break;
            c += hh;
        }
        if (level == 1)      { g_sel[0] = (unsigned)b; g_sel[1] = c; }
        else if (level == 2) { g_sel[2] = (unsigned)b; g_sel[3] = c; }
        else {
            g_sel[4] = (g_sel[0] << 20) | (g_sel[2] << 10) | (unsigned)b;  // K_T
            g_sel[5] = c;               // count of keys < K_T
            g_sel[6] = JRANK - c;       // ties to zero (in flat-index order)
        }
    }
}

// Collect flat indices of all elements whose key == K_T
__global__ void k_ties(
    const float4* __restrict__ s0, const float4* __restrict__ s1,
    const float4* __restrict__ s2, const float4* __restrict__ s3,
    const float4* __restrict__ s4, const float4* __restrict__ s5)
{
    const unsigned KT = g_sel[4];
    const int stride = gridDim.x * blockDim.x;
    for (int i4 = blockIdx.x * blockDim.x + threadIdx.x; i4 < NTOT4; i4 += stride) {
        float4 v = fetch4(i4, s0, s1, s2, s3, s4, s5);
        float vv[4] = {v.x, v.y, v.z, v.w};
        #pragma unroll
        for (int c = 0; c < 4; c++) {
            if (f2key(vv[c]) == KT) {
                unsigned p = atomicAdd(&g_sel[7], 1u);
                if (p < TIE_CAP) g_ties[p] = i4 * 4 + c;
            }
        }
    }
}

// Sort tie indices (tiny count); first `need` in flat-index order are zeroed.
// Stable-sort equivalence: zeroed  <=>  flat_idx < g_ties_sorted[need].
__global__ void k_tiesort() {
    int cnt = (int)g_sel[7];
    if (cnt > TIE_CAP) cnt = TIE_CAP;
    int need = (int)g_sel[6];
    for (int i = 1; i < cnt; i++) {
        int v = g_ties[i];
        int j = i - 1;
        while (j >= 0 && g_ties[j] > v) { g_ties[j + 1] = g_ties[j]; j--; }
        g_ties[j + 1] = v;
    }
    g_sel[8] = (need < cnt) ? (unsigned)g_ties[need] : 0xFFFFFFFFu;
}

// ---------------------------------------------------------------------------
// Mask apply: dst = keep ? w : 0
// ---------------------------------------------------------------------------
__global__ void k_apply(const float4* __restrict__ w, const float4* __restrict__ s,
                        float4* __restrict__ dst, int n4, unsigned flatoff)
{
    const unsigned KT = g_sel[4], tieth = g_sel[8];
    int i = blockIdx.x * blockDim.x + threadIdx.x;
    if (i >= n4) return;
    float4 wv = w[i], sv = s[i];
    float sa[4] = {sv.x, sv.y, sv.z, sv.w};
    float wa[4] = {wv.x, wv.y, wv.z, wv.w};
    unsigned fb = flatoff + 4u * (unsigned)i;
    #pragma unroll
    for (int c = 0; c < 4; c++) {
        unsigned key = f2key(sa[c]);
        bool keep = (key > KT) || (key == KT && (fb + c) >= tieth);
        if (!keep) wa[c] = 0.f;
    }
    dst[i] = make_float4(wa[0], wa[1], wa[2], wa[3]);
}

// ---------------------------------------------------------------------------
// fp32 SIMT GEMM:  C[M,N] = A[M,K] * B[N,K]^T + bias  (optional relu)
// 128x128 tile, BK=16, 256 threads, 8x8 per thread (split 4+4 rows/cols)
// ---------------------------------------------------------------------------
template<bool RELU>
__global__ void __launch_bounds__(256, 2) k_gemm(
    const float* __restrict__ A, const float* __restrict__ B,
    const float* __restrict__ bias, float* __restrict__ C, int K, int N)
{
    __shared__ float As[16][132];
    __shared__ float Bs[16][132];
    const int tid = threadIdx.x;
    const int tx = tid & 15;
    const int ty = tid >> 4;
    const int bm = blockIdx.y << 7;
    const int bn = blockIdx.x << 7;
    const int lrow = tid >> 2;          // 0..63 (also loads lrow+64)
    const int lk   = (tid & 3) << 2;    // 0,4,8,12

    const float* Ag = A + (size_t)(bm + lrow) * K + lk;
    const float* Bg = B + (size_t)(bn + lrow) * K + lk;
    const size_t half = (size_t)64 * K;

    float acc[8][8];
    #pragma unroll
    for (int i = 0; i < 8; i++)
        #pragma unroll
        for (int j = 0; j < 8; j++) acc[i][j] = 0.f;

    for (int kt = 0; kt < K; kt += 16) {
        float4 a0 = *(const float4*)(Ag + kt);
        float4 a1 = *(const float4*)(Ag + half + kt);
        float4 b0 = *(const float4*)(Bg + kt);
        float4 b1 = *(const float4*)(Bg + half + kt);
        As[lk + 0][lrow] = a0.x; As[lk + 1][lrow] = a0.y; As[lk + 2][lrow] = a0.z; As[lk + 3][lrow] = a0.w;
        As[lk + 0][lrow + 64] = a1.x; As[lk + 1][lrow + 64] = a1.y; As[lk + 2][lrow + 64] = a1.z; As[lk + 3][lrow + 64] = a1.w;
        Bs[lk + 0][lrow] = b0.x; Bs[lk + 1][lrow] = b0.y; Bs[lk + 2][lrow] = b0.z; Bs[lk + 3][lrow] = b0.w;
        Bs[lk + 0][lrow + 64] = b1.x; Bs[lk + 1][lrow + 64] = b1.y; Bs[lk + 2][lrow + 64] = b1.z; Bs[lk + 3][lrow + 64] = b1.w;
        __syncthreads();
        #pragma unroll
        for (int kk = 0; kk < 16; kk++) {
            float a[8], b[8];
            *(float4*)(a)     = *(const float4*)&As[kk][ty << 2];
            *(float4*)(a + 4) = *(const float4*)&As[kk][64 + (ty << 2)];
            *(float4*)(b)     = *(const float4*)&Bs[kk][tx << 2];
            *(float4*)(b + 4) = *(const float4*)&Bs[kk][64 + (tx << 2)];
            #pragma unroll
            for (int i = 0; i < 8; i++)
                #pragma unroll
                for (int j = 0; j < 8; j++)
                    acc[i][j] = fmaf(a[i], b[j], acc[i][j]);
        }
        __syncthreads();
    }

    #pragma unroll
    for (int i = 0; i < 8; i++) {
        int r = bm + ((i < 4) ? (ty * 4 + i) : (64 + ty * 4 + i - 4));
        #pragma unroll
        for (int jh = 0; jh < 2; jh++) {
            int c0 = bn + jh * 64 + tx * 4;
            float4 o;
            float* oa = (float*)&o;
            #pragma unroll
            for (int j = 0; j < 4; j++) {
                float v = acc[i][jh * 4 + j] + bias[c0 + j];
                if (RELU) v = fmaxf(v, 0.f);
                oa[j] = v;
            }
            *(float4*)&C[(size_t)r * N + c0] = o;
        }
    }
}

// ---------------------------------------------------------------------------
// Launch: select -> (apply + gemm) x3.  Graph-capturable: kernels only.
// ---------------------------------------------------------------------------
extern "C" void kernel_launch(void* const* d_in, const int* in_sizes, int n_in,
                              void* d_out, int out_size)
{
    const float* x  = (const float*)d_in[0];
    const float* W1 = (const float*)d_in[1];
    const float* b1 = (const float*)d_in[2];
    const float* W2 = (const float*)d_in[3];
    const float* b2 = (const float*)d_in[4];
    const float* W3 = (const float*)d_in[5];
    const float* b3 = (const float*)d_in[6];
    const float4* s0 = (const float4*)d_in[7];   // sW1
    const float4* s1 = (const float4*)d_in[8];   // sb1
    const float4* s2 = (const float4*)d_in[9];   // sW2
    const float4* s3 = (const float4*)d_in[10];  // sb2
    const float4* s4 = (const float4*)d_in[11];  // sW3
    const float4* s5 = (const float4*)d_in[12];  // sb3

    void* p;
    cudaGetSymbolAddress(&p, g_mw); float* mw = (float*)p;
    cudaGetSymbolAddress(&p, g_mb); float* mb = (float*)p;
    cudaGetSymbolAddress(&p, g_h1); float* h1 = (float*)p;
    cudaGetSymbolAddress(&p, g_h2); float* h2 = (float*)p;

    // ---- global top-k threshold (3-level radix select + stable ties) ----
    k_zero<<<1, 256>>>();
    k_hist<<<1024, 256>>>(1, s0, s1, s2, s3, s4, s5);
    k_scan<<<1, 256>>>(1);
    k_hist<<<1024, 256>>>(2, s0, s1, s2, s3, s4, s5);
    k_scan<<<1, 256>>>(2);
    k_hist<<<1024, 256>>>(3, s0, s1, s2, s3, s4, s5);
    k_scan<<<1, 256>>>(3);
    k_ties<<<1024, 256>>>(s0, s1, s2, s3, s4, s5);
    k_tiesort<<<1, 1>>>();

    // ---- layer 1: h1 = relu(x @ (W1*m)^T + b1*m) ----
    k_apply<<<(1048576 + 255) / 256, 256>>>((const float4*)W1, s0, (float4*)mw, 1048576, 0u);
    k_apply<<<4, 256>>>((const float4*)b1, s1, (float4*)mb, 1024, (unsigned)E0);
    k_gemm<true><<<dim3(32, 8), 256>>>(x, mw, mb, h1, 1024, 4096);

    // ---- layer 2: h2 = relu(h1 @ (W2*m)^T + b2*m) ----
    k_apply<<<16384, 256>>>((const float4*)W2, s2, (float4*)mw, 4194304, (unsigned)E1);
    k_apply<<<4, 256>>>((const float4*)b2, s3, (float4*)mb, 1024, (unsigned)E2);
    k_gemm<true><<<dim3(32, 8), 256>>>(h1, mw, mb, h2, 4096, 4096);

    // ---- layer 3: out = h2 @ (W3*m)^T + b3*m ----
    k_apply<<<4096, 256>>>((const float4*)W3, s4, (float4*)mw, 1048576, (unsigned)E3);
    k_apply<<<1, 256>>>((const float4*)b3, s5, (float4*)mb, 256, (unsigned)E4);
    k_gemm<false><<<dim3(8, 8), 256>>>(h2, mw, mb, (float*)d_out, 4096, 1024);
}

// round 5
// speedup vs baseline: 2.4020x; 2.4020x over previous
#include <cuda_runtime.h>
#include <cuda_bf16.h>
#include <cstdint>

// ---------------------------------------------------------------------------
// Problem constants (B=1024, D_IN=1024, D_H=4096, D_OUT=1024, SPARSITY=0.5)
// concat order: [sW1, sb1, sW2, sb2, sW3, sb3]
// n = 4194304 + 4096 + 16777216 + 4096 + 4194304 + 1024 = 25175040
// j = int(0.5*n) = 12587520
// ---------------------------------------------------------------------------
#define NTOT   25175040
#define NTOT4  6293760
#define JRANK  12587520u

#define E0 4194304
#define E1 4198400
#define E2 20975616
#define E3 20979712
#define E4 25174016
#define F0 1048576
#define F1 1049600
#define F2 5243904
#define F3 5244928
#define F4 6293504

#define CAND_CAP (1<<20)

// ---------------------------------------------------------------------------
// Device scratch
// ---------------------------------------------------------------------------
__device__ __align__(256) __nv_bfloat16 g_wh[16777216];
__device__ __align__(256) __nv_bfloat16 g_wl[16777216];
__device__ __align__(256) __nv_bfloat16 g_xh[1048576],  g_xl[1048576];
__device__ __align__(256) __nv_bfloat16 g_h1h[4194304], g_h1l[4194304];
__device__ __align__(256) __nv_bfloat16 g_h2h[4194304], g_h2l[4194304];
__device__ __align__(256) float    g_mb[4096];
__device__ unsigned g_hist1[4096];
__device__ unsigned g_sel[16];   // 0:bin1 1:cum1 4:KT 8:tieth 9:candcnt
__device__ unsigned g_candk[CAND_CAP];
__device__ unsigned g_candi[CAND_CAP];

// ---------------------------------------------------------------------------
// PTX helpers (baseline ISA only: cp.async / ldmatrix / mma.sync)
// ---------------------------------------------------------------------------
__device__ __forceinline__ uint32_t smem_u32(const void* p) {
    uint32_t a;
    asm("{ .reg .u64 t; cvta.to.shared.u64 t, %1; cvt.u32.u64 %0, t; }" : "=r"(a) : "l"(p));
    return a;
}
__device__ __forceinline__ void cp16(uint32_t dst, const void* src) {
    asm volatile("cp.async.cg.shared.global [%0], [%1], 16;" :: "r"(dst), "l"(src));
}
#define CP_COMMIT() asm volatile("cp.async.commit_group;" ::: "memory")

__device__ __forceinline__ void ldm_x4(uint32_t* r, uint32_t addr) {
    asm volatile("ldmatrix.sync.aligned.m8n8.x4.shared.b16 {%0,%1,%2,%3}, [%4];"
        : "=r"(r[0]), "=r"(r[1]), "=r"(r[2]), "=r"(r[3]) : "r"(addr));
}
__device__ __forceinline__ void mma_bf16(float* c, const uint32_t* a, const uint32_t* b) {
    asm volatile(
        "mma.sync.aligned.m16n8k16.row.col.f32.bf16.bf16.f32 "
        "{%0,%1,%2,%3}, {%4,%5,%6,%7}, {%8,%9}, {%0,%1,%2,%3};"
        : "+f"(c[0]), "+f"(c[1]), "+f"(c[2]), "+f"(c[3])
        : "r"(a[0]), "r"(a[1]), "r"(a[2]), "r"(a[3]), "r"(b[0]), "r"(b[1]));
}

// ---------------------------------------------------------------------------
// Selection: order-preserving key + segment fetch
// ---------------------------------------------------------------------------
__device__ __forceinline__ unsigned f2key(float f) {
    unsigned u = __float_as_uint(f);
    return (u & 0x80000000u) ? ~u : (u | 0x80000000u);
}
__device__ __forceinline__ float4 fetch4(int i4,
    const float4* __restrict__ s0, const float4* __restrict__ s1,
    const float4* __restrict__ s2, const float4* __restrict__ s3,
    const float4* __restrict__ s4, const float4* __restrict__ s5)
{
    if (i4 < F0) return s0[i4];
    if (i4 < F1) return s1[i4 - F0];
    if (i4 < F2) return s2[i4 - F1];
    if (i4 < F3) return s3[i4 - F2];
    if (i4 < F4) return s4[i4 - F3];
    return s5[i4 - F4];
}

__global__ void k_zero() {
    int t = threadIdx.x;
    for (int i = t; i < 4096; i += 256) g_hist1[i] = 0;
    if (t < 16) g_sel[t] = 0;
}

__global__ void k_hist1(
    const float4* __restrict__ s0, const float4* __restrict__ s1,
    const float4* __restrict__ s2, const float4* __restrict__ s3,
    const float4* __restrict__ s4, const float4* __restrict__ s5)
{
    __shared__ unsigned h[4096];
    for (int i = threadIdx.x; i < 4096; i += blockDim.x) h[i] = 0;
    __syncthreads();
    const int stride = gridDim.x * blockDim.x;
    for (int i4 = blockIdx.x * blockDim.x + threadIdx.x; i4 < NTOT4; i4 += stride) {
        float4 v = fetch4(i4, s0, s1, s2, s3, s4, s5);
        atomicAdd(&h[f2key(v.x) >> 20], 1u);
        atomicAdd(&h[f2key(v.y) >> 20], 1u);
        atomicAdd(&h[f2key(v.z) >> 20], 1u);
        atomicAdd(&h[f2key(v.w) >> 20], 1u);
    }
    __syncthreads();
    for (int i = threadIdx.x; i < 4096; i += blockDim.x) {
        unsigned c = h[i];
        if (c) atomicAdd(&g_hist1[i], c);
    }
}

__global__ void k_scan1() {
    __shared__ unsigned part[256];
    int t = threadIdx.x;
    unsigned s = 0;
    for (int i = 0; i < 16; i++) s += g_hist1[t * 16 + i];
    part[t] = s;
    __syncthreads();
    if (t == 0) {
        unsigned c = 0;
        int ch = 0;
        for (; ch < 255; ch++) { if (c + part[ch] > JRANK) break; c += part[ch]; }
        int b = ch * 16;
        for (;; b++) { unsigned hh = g_hist1[b]; if (c + hh > JRANK) break; c += hh; }
        g_sel[0] = (unsigned)b; g_sel[1] = c;
    }
}

__global__ void k_compact(
    const float4* __restrict__ s0, const float4* __restrict__ s1,
    const float4* __restrict__ s2, const float4* __restrict__ s3,
    const float4* __restrict__ s4, const float4* __restrict__ s5)
{
    const unsigned bin = g_sel[0];
    const int stride = gridDim.x * blockDim.x;
    for (int i4 = blockIdx.x * blockDim.x + threadIdx.x; i4 < NTOT4; i4 += stride) {
        float4 v = fetch4(i4, s0, s1, s2, s3, s4, s5);
        float vv[4] = {v.x, v.y, v.z, v.w};
        #pragma unroll
        for (int c = 0; c < 4; c++) {
            unsigned key = f2key(vv[c]);
            if ((key >> 20) == bin) {
                unsigned p = atomicAdd(&g_sel[9], 1u);
                if (p < CAND_CAP) { g_candk[p] = key; g_candi[p] = (unsigned)(i4 * 4 + c); }
            }
        }
    }
}

__global__ void k_finish() {
    __shared__ unsigned h[1024];
    __shared__ unsigned ties[2048];
    __shared__ unsigned sh_b2, sh_c2, sh_KT, sh_need, sh_tc;
    int t = threadIdx.x;
    unsigned cnt = g_sel[9]; if (cnt > CAND_CAP) cnt = CAND_CAP;

    h[t] = 0;
    if (t == 0) sh_tc = 0;
    __syncthreads();
    for (unsigned j = t; j < cnt; j += 1024) atomicAdd(&h[(g_candk[j] >> 10) & 1023u], 1u);
    __syncthreads();
    if (t == 0) {
        unsigned c = g_sel[1];
        int b = 0;
        for (;; b++) { if (c + h[b] > JRANK) break; c += h[b]; }
        sh_b2 = (unsigned)b; sh_c2 = c;
    }
    __syncthreads();
    unsigned b2 = sh_b2;
    h[t] = 0;
    __syncthreads();
    for (unsigned j = t; j < cnt; j += 1024) {
        unsigned k = g_candk[j];
        if (((k >> 10) & 1023u) == b2) atomicAdd(&h[k & 1023u], 1u);
    }
    __syncthreads();
    if (t == 0) {
        unsigned c = sh_c2;
        int b = 0;
        for (;; b++) { if (c + h[b] > JRANK) break; c += h[b]; }
        sh_KT = (g_sel[0] << 20) | (b2 << 10) | (unsigned)b;
        sh_need = JRANK - c;
    }
    __syncthreads();
    unsigned KT = sh_KT;
    for (unsigned j = t; j < cnt; j += 1024) {
        if (g_candk[j] == KT) {
            unsigned p = atomicAdd(&sh_tc, 1u);
            if (p < 2048) ties[p] = g_candi[j];
        }
    }
    __syncthreads();
    if (t == 0) {
        int n = (int)sh_tc; if (n > 2048) n = 2048;
        for (int i = 1; i < n; i++) {
            unsigned v = ties[i]; int j = i - 1;
            while (j >= 0 && ties[j] > v) { ties[j + 1] = ties[j]; j--; }
            ties[j + 1] = v;
        }
        g_sel[4] = KT;
        g_sel[8] = (sh_need < (unsigned)n) ? ties[sh_need] : 0xFFFFFFFFu;
    }
}

// ---------------------------------------------------------------------------
// Apply: masked weights -> bf16 hi/lo; masked bias -> fp32; x -> bf16 hi/lo
// ---------------------------------------------------------------------------
__global__ void k_applyw(const float4* __restrict__ w, const float4* __restrict__ s,
                         __nv_bfloat16* __restrict__ oh, __nv_bfloat16* __restrict__ ol,
                         int n4, unsigned flatoff)
{
    const unsigned KT = g_sel[4], tieth = g_sel[8];
    int i = blockIdx.x * blockDim.x + threadIdx.x;
    if (i >= n4) return;
    float4 wv = w[i], sv = s[i];
    float sa[4] = {sv.x, sv.y, sv.z, sv.w};
    float wa[4] = {wv.x, wv.y, wv.z, wv.w};
    unsigned fb = flatoff + 4u * (unsigned)i;
    ushort4 uh, ul;
    unsigned short* ph = (unsigned short*)&uh;
    unsigned short* pl = (unsigned short*)&ul;
    #pragma unroll
    for (int c = 0; c < 4; c++) {
        unsigned key = f2key(sa[c]);
        bool keep = (key > KT) || (key == KT && (fb + c) >= tieth);
        float v = keep ? wa[c] : 0.f;
        __nv_bfloat16 hi = __float2bfloat16(v);
        __nv_bfloat16 lo = __float2bfloat16(v - __bfloat162float(hi));
        ph[c] = __bfloat16_as_ushort(hi);
        pl[c] = __bfloat16_as_ushort(lo);
    }
    *(ushort4*)(oh + 4 * (size_t)i) = uh;
    *(ushort4*)(ol + 4 * (size_t)i) = ul;
}

__global__ void k_applyb(const float4* __restrict__ w, const float4* __restrict__ s,
                         float4* __restrict__ dst, int n4, unsigned flatoff)
{
    const unsigned KT = g_sel[4], tieth = g_sel[8];
    int i = blockIdx.x * blockDim.x + threadIdx.x;
    if (i >= n4) return;
    float4 wv = w[i], sv = s[i];
    float sa[4] = {sv.x, sv.y, sv.z, sv.w};
    float wa[4] = {wv.x, wv.y, wv.z, wv.w};
    unsigned fb = flatoff + 4u * (unsigned)i;
    #pragma unroll
    for (int c = 0; c < 4; c++) {
        unsigned key = f2key(sa[c]);
        bool keep = (key > KT) || (key == KT && (fb + c) >= tieth);
        if (!keep) wa[c] = 0.f;
    }
    dst[i] = make_float4(wa[0], wa[1], wa[2], wa[3]);
}

__global__ void k_split(const float4* __restrict__ x,
                        __nv_bfloat16* __restrict__ oh, __nv_bfloat16* __restrict__ ol, int n4)
{
    int i = blockIdx.x * blockDim.x + threadIdx.x;
    if (i >= n4) return;
    float4 v = x[i];
    float va[4] = {v.x, v.y, v.z, v.w};
    ushort4 uh, ul;
    unsigned short* ph = (unsigned short*)&uh;
    unsigned short* pl = (unsigned short*)&ul;
    #pragma unroll
    for (int c = 0; c < 4; c++) {
        __nv_bfloat16 hi = __float2bfloat16(va[c]);
        __nv_bfloat16 lo = __float2bfloat16(va[c] - __bfloat162float(hi));
        ph[c] = __bfloat16_as_ushort(hi);
        pl[c] = __bfloat16_as_ushort(lo);
    }
    *(ushort4*)(oh + 4 * (size_t)i) = uh;
    *(ushort4*)(ol + 4 * (size_t)i) = ul;
}

// ---------------------------------------------------------------------------
// mma.sync bf16 split GEMM: C[M,N] = A[M,K]*B[N,K]^T + bias
//   C ~= Ahi*Bhi + Alo*Bhi + Ahi*Blo   (fp32 accumulate)
// CTA tile 128x128, BK=64, 256 threads (8 warps, 2m x 4n, warp tile 64x32)
// Row-padded SMEM (64+8 bf16 = 144B stride) -> conflict-free ldmatrix.
// Double-buffered cp.async pipeline.
// MODE 0: relu + bf16 hi/lo outputs; MODE 1: fp32 output.
// ---------------------------------------------------------------------------
#define ROWB    144
#define TILEB   18432          // 128 * 144
#define BUFB    73728          // 4 tiles
#define MG_SMEM 147456         // 2 buffers

__device__ __forceinline__ void stage_tile(const __nv_bfloat16* __restrict__ g,
                                           int row0, int k0, int K, uint32_t sdst)
{
    int tid = threadIdx.x;
    // 128 rows x 64 bf16 = 128 rows x 8 chunks of 16B = 1024 cp.async ops
    #pragma unroll
    for (int i = 0; i < 4; i++) {
        int s = tid + (i << 8);
        int r = s >> 3, sub = s & 7;
        cp16(sdst + (uint32_t)(r * ROWB + sub * 16),
             g + (size_t)(row0 + r) * K + k0 + sub * 8);
    }
}

__device__ __forceinline__ void stage_buf(
    const __nv_bfloat16* Ah, const __nv_bfloat16* Al,
    const __nv_bfloat16* Bh, const __nv_bfloat16* Bl,
    int bm, int bn, int k0, int K, uint32_t sbase)
{
    stage_tile(Ah, bm, k0, K, sbase);
    stage_tile(Al, bm, k0, K, sbase + TILEB);
    stage_tile(Bh, bn, k0, K, sbase + 2 * TILEB);
    stage_tile(Bl, bn, k0, K, sbase + 3 * TILEB);
}

template<int MODE>
__global__ void __launch_bounds__(256, 1) k_mgemm(
    const __nv_bfloat16* __restrict__ Ah, const __nv_bfloat16* __restrict__ Al,
    const __nv_bfloat16* __restrict__ Bh, const __nv_bfloat16* __restrict__ Bl,
    const float* __restrict__ bias,
    __nv_bfloat16* __restrict__ Oh, __nv_bfloat16* __restrict__ Ol,
    float* __restrict__ Of, int N, int K)
{
    extern __shared__ char smem[];
    const uint32_t sb = smem_u32(smem);
    const int tid = threadIdx.x, lane = tid & 31, wid = tid >> 5;
    const int wm = wid & 1, wn = wid >> 1;
    const int bm = blockIdx.y << 7, bn = blockIdx.x << 7;

    float acc[4][4][4];
    #pragma unroll
    for (int f = 0; f < 4; f++)
        #pragma unroll
        for (int g = 0; g < 4; g++)
            #pragma unroll
            for (int v = 0; v < 4; v++) acc[f][g][v] = 0.f;

    const int nc = K >> 6;
    stage_buf(Ah, Al, Bh, Bl, bm, bn, 0, K, sb);
    CP_COMMIT();
    stage_buf(Ah, Al, Bh, Bl, bm, bn, 64, K, sb + BUFB);
    CP_COMMIT();

    const int arow = wm * 64 + (lane & 15);
    const int acolb = ((lane >> 4) << 3) * 2;
    const int brow = wn * 32 + (lane & 7) + (((lane >> 4) & 1) << 3);
    const int bcolb = (((lane >> 3) & 1) << 3) * 2;

    for (int i = 0; i < nc; i++) {
        if (i < nc - 1) asm volatile("cp.async.wait_group 1;" ::: "memory");
        else           asm volatile("cp.async.wait_group 0;" ::: "memory");
        __syncthreads();

        const uint32_t base = sb + (uint32_t)(i & 1) * BUFB;
        #pragma unroll
        for (int kk = 0; kk < 4; kk++) {
            uint32_t Ahf[4][4], Alf[4][4], Bhf[2][4], Blf[2][4];
            const uint32_t ak = (uint32_t)(kk * 32) + acolb;   // bytes within row
            const uint32_t bk = (uint32_t)(kk * 32) + bcolb;
            #pragma unroll
            for (int f = 0; f < 4; f++) {
                uint32_t ra = base + (uint32_t)((arow + f * 16) * ROWB) + ak;
                ldm_x4(Ahf[f], ra);
                ldm_x4(Alf[f], ra + TILEB);
            }
            #pragma unroll
            for (int p = 0; p < 2; p++) {
                uint32_t rb = base + 2u * TILEB + (uint32_t)((brow + p * 16) * ROWB) + bk;
                ldm_x4(Bhf[p], rb);
                ldm_x4(Blf[p], rb + TILEB);
            }
            #pragma unroll
            for (int f = 0; f < 4; f++)
                #pragma unroll
                for (int g = 0; g < 4; g++) {
                    const uint32_t* bh = &Bhf[g >> 1][(g & 1) << 1];
                    const uint32_t* bl = &Blf[g >> 1][(g & 1) << 1];
                    mma_bf16(acc[f][g], Ahf[f], bh);
                    mma_bf16(acc[f][g], Alf[f], bh);
                    mma_bf16(acc[f][g], Ahf[f], bl);
                }
        }

        if (i + 2 < nc) {
            __syncthreads();
            stage_buf(Ah, Al, Bh, Bl, bm, bn, (i + 2) << 6, K, base);
            CP_COMMIT();
        }
    }

    // epilogue: bias (+relu) then direct global stores
    #pragma unroll
    for (int f = 0; f < 4; f++) {
        #pragma unroll
        for (int g = 0; g < 4; g++) {
            int r0 = bm + wm * 64 + f * 16 + (lane >> 2);
            int c0 = bn + wn * 32 + g * 8 + ((lane & 3) << 1);
            float bv0 = bias[c0], bv1 = bias[c0 + 1];
            #pragma unroll
            for (int h = 0; h < 2; h++) {
                int r = r0 + h * 8;
                float v0 = acc[f][g][2 * h + 0] + bv0;
                float v1 = acc[f][g][2 * h + 1] + bv1;
                if (MODE == 0) {
                    v0 = fmaxf(v0, 0.f); v1 = fmaxf(v1, 0.f);
                    __nv_bfloat16 h0 = __float2bfloat16(v0), h1 = __float2bfloat16(v1);
                    __nv_bfloat16 l0 = __float2bfloat16(v0 - __bfloat162float(h0));
                    __nv_bfloat16 l1 = __float2bfloat16(v1 - __bfloat162float(h1));
                    ushort2 uh = make_ushort2(__bfloat16_as_ushort(h0), __bfloat16_as_ushort(h1));
                    ushort2 ul = make_ushort2(__bfloat16_as_ushort(l0), __bfloat16_as_ushort(l1));
                    *(ushort2*)(Oh + (size_t)r * N + c0) = uh;
                    *(ushort2*)(Ol + (size_t)r * N + c0) = ul;
                } else {
                    float2 o = make_float2(v0, v1);
                    *(float2*)(Of + (size_t)r * N + c0) = o;
                }
            }
        }
    }
}

// ---------------------------------------------------------------------------
// Launch
// ---------------------------------------------------------------------------
extern "C" void kernel_launch(void* const* d_in, const int* in_sizes, int n_in,
                              void* d_out, int out_size)
{
    const float* x  = (const float*)d_in[0];
    const float* W1 = (const float*)d_in[1];
    const float* b1 = (const float*)d_in[2];
    const float* W2 = (const float*)d_in[3];
    const float* b2 = (const float*)d_in[4];
    const float* W3 = (const float*)d_in[5];
    const float* b3 = (const float*)d_in[6];
    const float4* s0 = (const float4*)d_in[7];
    const float4* s1 = (const float4*)d_in[8];
    const float4* s2 = (const float4*)d_in[9];
    const float4* s3 = (const float4*)d_in[10];
    const float4* s4 = (const float4*)d_in[11];
    const float4* s5 = (const float4*)d_in[12];

    void* p;
    cudaGetSymbolAddress(&p, g_wh);  __nv_bfloat16* wh  = (__nv_bfloat16*)p;
    cudaGetSymbolAddress(&p, g_wl);  __nv_bfloat16* wl  = (__nv_bfloat16*)p;
    cudaGetSymbolAddress(&p, g_xh);  __nv_bfloat16* xh  = (__nv_bfloat16*)p;
    cudaGetSymbolAddress(&p, g_xl);  __nv_bfloat16* xl  = (__nv_bfloat16*)p;
    cudaGetSymbolAddress(&p, g_h1h); __nv_bfloat16* h1h = (__nv_bfloat16*)p;
    cudaGetSymbolAddress(&p, g_h1l); __nv_bfloat16* h1l = (__nv_bfloat16*)p;
    cudaGetSymbolAddress(&p, g_h2h); __nv_bfloat16* h2h = (__nv_bfloat16*)p;
    cudaGetSymbolAddress(&p, g_h2l); __nv_bfloat16* h2l = (__nv_bfloat16*)p;
    cudaGetSymbolAddress(&p, g_mb);  float* mb = (float*)p;

    cudaFuncSetAttribute(k_mgemm<0>, cudaFuncAttributeMaxDynamicSharedMemorySize, MG_SMEM);
    cudaFuncSetAttribute(k_mgemm<1>, cudaFuncAttributeMaxDynamicSharedMemorySize, MG_SMEM);

    // ---- selection: level-1 hist + scan, compact selected bin, finish ----
    k_zero<<<1, 256>>>();
    k_hist1<<<1024, 256>>>(s0, s1, s2, s3, s4, s5);
    k_scan1<<<1, 256>>>();
    k_compact<<<1024, 256>>>(s0, s1, s2, s3, s4, s5);
    k_finish<<<1, 1024>>>();

    // ---- x split ----
    k_split<<<1024, 256>>>((const float4*)x, xh, xl, 262144);

    // ---- layer 1 ----
    k_applyw<<<4096, 256>>>((const float4*)W1, s0, wh, wl, 1048576, 0u);
    k_applyb<<<4, 256>>>((const float4*)b1, s1, (float4*)mb, 1024, (unsigned)E0);
    k_mgemm<0><<<dim3(32, 8), 256, MG_SMEM>>>(xh, xl, wh, wl, mb, h1h, h1l, nullptr, 4096, 1024);

    // ---- layer 2 ----
    k_applyw<<<16384, 256>>>((const float4*)W2, s2, wh, wl, 4194304, (unsigned)E1);
    k_applyb<<<4, 256>>>((const float4*)b2, s3, (float4*)mb, 1024, (unsigned)E2);
    k_mgemm<0><<<dim3(32, 8), 256, MG_SMEM>>>(h1h, h1l, wh, wl, mb, h2h, h2l, nullptr, 4096, 4096);

    // ---- layer 3 ----
    k_applyw<<<4096, 256>>>((const float4*)W3, s4, wh, wl, 1048576, (unsigned)E3);
    k_applyb<<<1, 256>>>((const float4*)b3, s5, (float4*)mb, 256, (unsigned)E4);
    k_mgemm<1><<<dim3(8, 8), 256, MG_SMEM>>>(h2h, h2l, wh, wl, mb, nullptr, nullptr, (float*)d_out, 1024, 4096);
}